// round 1
// baseline (speedup 1.0000x reference)
#include <cuda_runtime.h>
#include <cstdint>

#define CC   4
#define HH   4096
#define WW   4096
#define NPIX (HH*WW)          // 16777216
#define TT   8
#define THW  512              // tile height/width
#define BINS 256
#define AREA (THW*THW)        // 262144
#define CLV  40960            // int(40.0 * AREA / BINS)

// ---- scratch (static device globals: the sanctioned no-alloc workaround) ----
__device__ unsigned short      g_q[(size_t)CC * NPIX];        // low 8 bits: quantized value, bit 8: mask
__device__ int                 g_hist[CC][TT*TT][BINS];
__device__ unsigned char       g_lut[CC][TT*TT][BINS];
__device__ int                 g_vmin1[CC], g_vmax1[CC];      // float bits (positive-domain int trick)
__device__ int                 g_vmin2[CC], g_vmax2[CC];
__device__ unsigned int        g_nz[CC];
__device__ unsigned long long  g_sum[CC];

// ------------------------------------------------------------------ init ----
__global__ void k_init() {
    int i = blockIdx.x * blockDim.x + threadIdx.x;   // 65536 threads exactly
    ((int*)g_hist)[i] = 0;
    if (i < CC) {
        g_vmin1[i] = 0x7F800000;        // +inf
        g_vmax1[i] = (int)0xFF800000;   // -inf
        g_vmin2[i] = 0x7F800000;
        g_vmax2[i] = (int)0xFF800000;
        g_nz[i]  = 0u;
        g_sum[i] = 0ull;
    }
}

// --------------------------------------------------- pass 1: masked min/max --
__global__ void k_minmax(const float* __restrict__ X) {
    int c = blockIdx.y;
    const float4* p = (const float4*)(X + (size_t)c * NPIX);
    float vmin = __int_as_float(0x7F800000);
    float vmax = __int_as_float((int)0xFF800000);
    int stride = gridDim.x * blockDim.x;
    for (int i = blockIdx.x * blockDim.x + threadIdx.x; i < NPIX / 4; i += stride) {
        float4 v = p[i];
        if (v.x > 0.f) { vmin = fminf(vmin, v.x); vmax = fmaxf(vmax, v.x); }
        if (v.y > 0.f) { vmin = fminf(vmin, v.y); vmax = fmaxf(vmax, v.y); }
        if (v.z > 0.f) { vmin = fminf(vmin, v.z); vmax = fmaxf(vmax, v.z); }
        if (v.w > 0.f) { vmin = fminf(vmin, v.w); vmax = fmaxf(vmax, v.w); }
    }
    #pragma unroll
    for (int o = 16; o; o >>= 1) {
        vmin = fminf(vmin, __shfl_down_sync(0xffffffffu, vmin, o));
        vmax = fmaxf(vmax, __shfl_down_sync(0xffffffffu, vmax, o));
    }
    if ((threadIdx.x & 31) == 0) {
        atomicMin(&g_vmin1[c], __float_as_int(vmin));   // candidates all > 0 -> int order ok
        atomicMax(&g_vmax1[c], __float_as_int(vmax));
    }
}

// -------------------------- pass 2: quantize + tile histograms + nz stats ----
// One block = 16 consecutive rows (strictly inside one tile row). 256 threads.
__global__ void k_quant(const float* __restrict__ X) {
    int c   = blockIdx.y;
    int tid = threadIdx.x;
    __shared__ int sh[TT * BINS];                 // 8 x-tiles * 256 bins
    for (int j = tid; j < TT * BINS; j += 256) sh[j] = 0;
    __syncthreads();

    float vmin = __int_as_float(g_vmin1[c]);
    float vmax = __int_as_float(g_vmax1[c]);
    bool  cond = vmax > 0.0f;                     // == any(mask) since masked x > 0
    float rng  = fmaxf(vmax - vmin, 1e-12f);

    const float4* p = (const float4*)(X + (size_t)c * NPIX);
    ushort4*      q = (ushort4*)(g_q + (size_t)c * NPIX);

    int base = blockIdx.x * (16 * (WW / 4));      // float4 index base (16 rows)
    int nzc = 0; unsigned int nzs = 0;

    #pragma unroll 4
    for (int it = 0; it < 64; ++it) {
        int i = base + it * 256 + tid;
        float4 v = p[i];
        int tx = (i & ((WW / 4) - 1)) >> 7;       // 128 float4 per 512-px tile
        float xs[4] = {v.x, v.y, v.z, v.w};
        unsigned short r[4];
        #pragma unroll
        for (int k = 0; k < 4; k++) {
            float x = xs[k];
            bool  m = x > 0.0f;
            float t = m ? (cond ? (x - vmin) / rng : 0.0f) : x;
            float fb = floorf(t * 255.0f);
            fb = fminf(fmaxf(fb, 0.0f), 255.0f);
            int b = (int)fb;
            atomicAdd(&sh[tx * BINS + b], 1);
            nzc += (b != 0);
            nzs += (unsigned int)b;               // b==0 adds nothing
            r[k] = (unsigned short)(b | (m ? 0x100 : 0));
        }
        ushort4 o; o.x = r[0]; o.y = r[1]; o.z = r[2]; o.w = r[3];
        q[i] = o;
    }
    __syncthreads();

    int ty = blockIdx.x >> 5;                     // 32 blocks per tile row
    for (int j = tid; j < TT * BINS; j += 256) {
        int v = sh[j];
        if (v) atomicAdd(&g_hist[c][ty * TT + (j >> 8)][j & 255], v);
    }
    #pragma unroll
    for (int o = 16; o; o >>= 1) {
        nzc += __shfl_down_sync(0xffffffffu, nzc, o);
        nzs += __shfl_down_sync(0xffffffffu, nzs, o);
    }
    if ((tid & 31) == 0) {
        atomicAdd(&g_nz[c], (unsigned int)nzc);
        atomicAdd(&g_sum[c], (unsigned long long)nzs);
    }
}

// ------------------- pass 3: CLAHE clip + redistribution + CDF -> u8 LUT -----
// One block per (channel, tile). 256 threads = 256 bins. All-integer (exact).
__global__ void k_lut() {
    int c = blockIdx.y, tile = blockIdx.x, t = threadIdx.x;
    __shared__ int s[BINS];

    unsigned int nz = g_nz[c];
    int mean = 0;
    if (nz > 0) mean = (int)(g_sum[c] / (unsigned long long)nz);  // floor(sum/nz)

    int h = g_hist[c][tile][t];
    if (nz > 0 && mean != 0) {                    // hist of `filled`: move bin0 -> mean
        int h0 = g_hist[c][tile][0];
        if (t == mean) h += h0;
        if (t == 0)    h  = 0;
    }

    int exc = max(h - CLV, 0);
    s[t] = exc; __syncthreads();
    #pragma unroll
    for (int o = 128; o; o >>= 1) { if (t < o) s[t] += s[t + o]; __syncthreads(); }
    int excess = s[0];
    __syncthreads();

    h = min(h, CLV);
    int batch = excess >> 8;
    int resid = excess & 255;
    int step  = 256 / max(resid, 1);              // == max(floor(256/max(r,1)),1)
    h += batch + (((t % step) == 0 && (t / step) < resid) ? 1 : 0);

    // inclusive scan (Hillis-Steele)
    s[t] = h; __syncthreads();
    #pragma unroll
    for (int o = 1; o < 256; o <<= 1) {
        int v = (t >= o) ? s[t - o] : 0;
        __syncthreads();
        s[t] += v;
        __syncthreads();
    }
    float lut = rintf((float)s[t] * (255.0f / (float)AREA));      // round-half-even == jnp.round
    lut = fminf(fmaxf(lut, 0.0f), 255.0f);
    g_lut[c][tile][t] = (unsigned char)lut;
}

// ----------- passes 4/5: bilinear LUT apply; FINAL=false -> y min/max,
// ----------- FINAL=true -> rescale + write output -----------------------------
template <bool FINAL>
__global__ void k_apply(float* __restrict__ out) {
    int c = blockIdx.y;
    __shared__ unsigned char lutS[TT * TT * BINS];                // 16 KB
    {
        const uint4* src = (const uint4*)g_lut[c];
        uint4* dst = (uint4*)lutS;
        for (int j = threadIdx.x; j < (TT * TT * BINS) / 16; j += 256) dst[j] = src[j];
    }
    __shared__ int s_mean, s_nzf;
    if (threadIdx.x == 0) {
        unsigned int nz = g_nz[c];
        s_nzf  = (nz > 0);
        s_mean = nz ? (int)(g_sum[c] / (unsigned long long)nz) : 0;
    }
    __syncthreads();
    const int mean = s_mean, nzf = s_nzf;

    float vmin2 = 0.f, rng2 = 1.f; bool cond2 = false;
    if (FINAL) {
        bool anym = __int_as_float(g_vmax1[c]) > 0.0f;
        vmin2 = __int_as_float(g_vmin2[c]);
        float vmax2 = __int_as_float(g_vmax2[c]);
        cond2 = anym && (vmax2 > 0.0f);
        rng2  = fmaxf(vmax2 - vmin2, 1e-12f);
    }

    const ushort4* q = (const ushort4*)(g_q + (size_t)c * NPIX);
    float lmin = __int_as_float(0x7F800000);
    float lmax = __int_as_float((int)0xFF800000);
    int stride = gridDim.x * blockDim.x;

    for (int i = blockIdx.x * blockDim.x + threadIdx.x; i < NPIX / 4; i += stride) {
        ushort4 qq = q[i];
        int row  = i >> 10;                        // 1024 float4-groups per row
        int col0 = (i & 1023) << 2;
        float fy  = ((float)row + 0.5f) * (1.0f / (float)THW) - 0.5f;
        float ffy = floorf(fy);
        int y0 = min(max((int)ffy, 0), TT - 1);
        int y1 = min(y0 + 1, TT - 1);
        float wy = fy - ffy, omy = 1.0f - wy;

        unsigned short qs[4] = {qq.x, qq.y, qq.z, qq.w};
        float res[4];
        #pragma unroll
        for (int k = 0; k < 4; k++) {
            int col = col0 + k;
            float fx  = ((float)col + 0.5f) * (1.0f / (float)THW) - 0.5f;
            float ffx = floorf(fx);
            int x0 = min(max((int)ffx, 0), TT - 1);
            int x1 = min(x0 + 1, TT - 1);
            float wx = fx - ffx, omx = 1.0f - wx;

            int v   = qs[k] & 255;
            int msk = qs[k] >> 8;
            int f   = (v == 0 && nzf) ? mean : v;

            float v00 = (float)lutS[((y0 << 3) + x0) * BINS + f];
            float v01 = (float)lutS[((y0 << 3) + x1) * BINS + f];
            float v10 = (float)lutS[((y1 << 3) + x0) * BINS + f];
            float v11 = (float)lutS[((y1 << 3) + x1) * BINS + f];

            float eq = v00 * omy * omx + v01 * omy * wx + v10 * wy * omx + v11 * wy * wx;
            float y  = (v == 0) ? 0.0f : eq / 255.0f;

            if (FINAL) {
                float scaled = (y - vmin2) / rng2 * 0.99607843f + 0.003921569f;  // (hi-lo), lo
                res[k] = msk ? (cond2 ? scaled : 0.003921569f) : y;
            } else {
                if (msk) { lmin = fminf(lmin, y); lmax = fmaxf(lmax, y); }
            }
        }
        if (FINAL) {
            float4 o4; o4.x = res[0]; o4.y = res[1]; o4.z = res[2]; o4.w = res[3];
            ((float4*)out)[(size_t)c * (NPIX / 4) + i] = o4;
        }
    }

    if (!FINAL) {
        #pragma unroll
        for (int o = 16; o; o >>= 1) {
            lmin = fminf(lmin, __shfl_down_sync(0xffffffffu, lmin, o));
            lmax = fmaxf(lmax, __shfl_down_sync(0xffffffffu, lmax, o));
        }
        if ((threadIdx.x & 31) == 0) {            // y >= 0 -> int-bit atomics valid
            atomicMin(&g_vmin2[c], __float_as_int(lmin));
            atomicMax(&g_vmax2[c], __float_as_int(lmax));
        }
    }
}

// ---------------------------------------------------------------------------
extern "C" void kernel_launch(void* const* d_in, const int* in_sizes, int n_in,
                              void* d_out, int out_size) {
    const float* X = (const float*)d_in[0];
    float* out = (float*)d_out;

    k_init<<<256, 256>>>();

    dim3 g1(1024, CC); k_minmax<<<g1, 256>>>(X);
    dim3 g2(256,  CC); k_quant <<<g2, 256>>>(X);
    dim3 g3(TT*TT, CC); k_lut  <<<g3, 256>>>();
    dim3 g4(1024, CC);
    k_apply<false><<<g4, 256>>>(out);
    k_apply<true> <<<g4, 256>>>(out);
}

// round 2
// speedup vs baseline: 1.2916x; 1.2916x over previous
#include <cuda_runtime.h>
#include <cstdint>

#define CC   4
#define HH   4096
#define WW   4096
#define NPIX (HH*WW)          // 16777216
#define TT   8
#define THW  512
#define BINS 256
#define AREA (THW*THW)        // 262144
#define CLV  40960            // int(40.0 * AREA / BINS)
#define MMB  1024             // minmax blocks per channel

// ---------------- scratch (static device globals; no allocation) ------------
__device__ unsigned char      g_q[(size_t)CC * NPIX];        // quantized value 0..255
__device__ unsigned char      g_m[(size_t)CC * NPIX / 4];    // mask nibble per float4 group
__device__ int                g_hist[CC][TT*TT][BINS];
__device__ unsigned char      g_lut[CC][TT*TT][BINS];
__device__ float2             g_part[CC * MMB];              // per-block (min,max) partials
__device__ int                g_vmin2[CC], g_vmax2[CC];      // float bits (y >= 0 -> int trick)
__device__ unsigned int       g_nz[CC], g_flag0[CC];
__device__ unsigned long long g_sum[CC];

#define F_INF  __int_as_float(0x7F800000)
#define F_NINF __int_as_float((int)0xFF800000)

// ---------------- pass 1: per-block masked min/max partials (+ init) --------
__global__ void k_minmax(const float* __restrict__ X) {
    int c = blockIdx.y, bx = blockIdx.x, tid = threadIdx.x;

    // fused init: zero hist (65536 ints over 4096 blocks = 16 each) + scalars
    if (tid < 16) ((int*)g_hist)[(c * MMB + bx) * 16 + tid] = 0;
    if (c == 0 && bx == 0 && tid < CC) {
        g_vmin2[tid] = 0x7F800000;
        g_vmax2[tid] = (int)0xFF800000;
        g_nz[tid] = 0u; g_flag0[tid] = 0u; g_sum[tid] = 0ull;
    }

    const float4* p = (const float4*)(X + (size_t)c * NPIX);
    int base = bx * 4096;
    float vmin = F_INF, vmax = F_NINF;
    #pragma unroll 4
    for (int it = 0; it < 16; ++it) {
        float4 v = p[base + it * 256 + tid];
        if (v.x > 0.f) { vmin = fminf(vmin, v.x); vmax = fmaxf(vmax, v.x); }
        if (v.y > 0.f) { vmin = fminf(vmin, v.y); vmax = fmaxf(vmax, v.y); }
        if (v.z > 0.f) { vmin = fminf(vmin, v.z); vmax = fmaxf(vmax, v.z); }
        if (v.w > 0.f) { vmin = fminf(vmin, v.w); vmax = fmaxf(vmax, v.w); }
    }
    __shared__ float smn[8], smx[8];
    #pragma unroll
    for (int o = 16; o; o >>= 1) {
        vmin = fminf(vmin, __shfl_down_sync(0xffffffffu, vmin, o));
        vmax = fmaxf(vmax, __shfl_down_sync(0xffffffffu, vmax, o));
    }
    if ((tid & 31) == 0) { smn[tid >> 5] = vmin; smx[tid >> 5] = vmax; }
    __syncthreads();
    if (tid == 0) {
        float a = F_INF, b = F_NINF;
        #pragma unroll
        for (int j = 0; j < 8; j++) { a = fminf(a, smn[j]); b = fmaxf(b, smx[j]); }
        g_part[c * MMB + bx] = make_float2(a, b);
    }
}

// --------- pass 2: quantize + tile histograms + nz stats + zero-mask flag ---
// One block = 8 rows (inside one tile row). 256 threads. 512 blocks/channel.
__global__ void k_quant(const float* __restrict__ X) {
    int c = blockIdx.y, bx = blockIdx.x, tid = threadIdx.x;
    __shared__ int sh[TT * BINS];
    __shared__ float smn[8], smx[8], sfin[2];

    // reduce global partials -> channel min/max
    float vmin = F_INF, vmax = F_NINF;
    for (int j = tid; j < MMB; j += 256) {
        float2 pp = g_part[c * MMB + j];
        vmin = fminf(vmin, pp.x); vmax = fmaxf(vmax, pp.y);
    }
    #pragma unroll
    for (int o = 16; o; o >>= 1) {
        vmin = fminf(vmin, __shfl_down_sync(0xffffffffu, vmin, o));
        vmax = fmaxf(vmax, __shfl_down_sync(0xffffffffu, vmax, o));
    }
    if ((tid & 31) == 0) { smn[tid >> 5] = vmin; smx[tid >> 5] = vmax; }
    for (int j = tid; j < TT * BINS; j += 256) sh[j] = 0;
    __syncthreads();
    if (tid == 0) {
        float a = F_INF, b = F_NINF;
        #pragma unroll
        for (int j = 0; j < 8; j++) { a = fminf(a, smn[j]); b = fmaxf(b, smx[j]); }
        sfin[0] = a; sfin[1] = b;
    }
    __syncthreads();
    vmin = sfin[0]; vmax = sfin[1];
    bool  cond = vmax > 0.0f;
    float rng  = fmaxf(vmax - vmin, 1e-12f);

    const float4* p  = (const float4*)(X + (size_t)c * NPIX);
    uchar4*       q8 = (uchar4*)(g_q + (size_t)c * NPIX);
    unsigned char* mp = g_m + (size_t)c * (NPIX / 4);

    int base = bx * 8192;                         // 8 rows of 1024 float4
    int nzc = 0; unsigned int nzs = 0; bool az = false;

    #pragma unroll 4
    for (int it = 0; it < 32; ++it) {
        int i = base + it * 256 + tid;
        float4 v = p[i];
        int tx = (i & 1023) >> 7;
        float xs[4] = {v.x, v.y, v.z, v.w};
        unsigned char r[4]; unsigned int nib = 0;
        #pragma unroll
        for (int k = 0; k < 4; k++) {
            float x = xs[k];
            bool  m = x > 0.0f;
            float t = m ? (cond ? (x - vmin) / rng : 0.0f) : x;
            float fb = fminf(fmaxf(floorf(t * 255.0f), 0.0f), 255.0f);
            int b = (int)fb;
            atomicAdd(&sh[tx * BINS + b], 1);
            nzc += (b != 0);
            nzs += (unsigned int)b;
            az  |= (m && b == 0);
            r[k] = (unsigned char)b;
            nib |= (m ? 1u : 0u) << k;
        }
        uchar4 o; o.x = r[0]; o.y = r[1]; o.z = r[2]; o.w = r[3];
        q8[i] = o;
        mp[i] = (unsigned char)nib;
    }
    __syncthreads();

    int ty = bx >> 6;                             // 64 blocks per tile row
    for (int j = tid; j < TT * BINS; j += 256) {
        int v = sh[j];
        if (v) atomicAdd(&g_hist[c][ty * TT + (j >> 8)][j & 255], v);
    }
    unsigned int bal = __ballot_sync(0xffffffffu, az);
    #pragma unroll
    for (int o = 16; o; o >>= 1) {
        nzc += __shfl_down_sync(0xffffffffu, nzc, o);
        nzs += __shfl_down_sync(0xffffffffu, nzs, o);
    }
    if ((tid & 31) == 0) {
        atomicAdd(&g_nz[c], (unsigned int)nzc);
        atomicAdd(&g_sum[c], (unsigned long long)nzs);
        if (bal) atomicOr(&g_flag0[c], 1u);
    }
}

// ------------- pass 3: clip + redistribute + CDF -> u8 LUT (+ flag seed) ----
__global__ void k_lut() {
    int c = blockIdx.y, tile = blockIdx.x, t = threadIdx.x;
    __shared__ int s[BINS];

    if (tile == 0 && t == 0 && g_flag0[c]) {      // masked v==0 pixel exists -> y=0 candidate
        g_vmin2[c] = 0;                           // bits of 0.0f
        g_vmax2[c] = 0;
    }

    unsigned int nz = g_nz[c];
    int mean = 0;
    if (nz > 0) mean = (int)(g_sum[c] / (unsigned long long)nz);

    int h = g_hist[c][tile][t];
    if (nz > 0 && mean != 0) {
        int h0 = g_hist[c][tile][0];
        if (t == mean) h += h0;
        if (t == 0)    h  = 0;
    }

    int exc = max(h - CLV, 0);
    s[t] = exc; __syncthreads();
    #pragma unroll
    for (int o = 128; o; o >>= 1) { if (t < o) s[t] += s[t + o]; __syncthreads(); }
    int excess = s[0];
    __syncthreads();

    h = min(h, CLV);
    int batch = excess >> 8;
    int resid = excess & 255;
    int step  = 256 / max(resid, 1);
    h += batch + (((t % step) == 0 && (t / step) < resid) ? 1 : 0);

    s[t] = h; __syncthreads();
    #pragma unroll
    for (int o = 1; o < 256; o <<= 1) {
        int v = (t >= o) ? s[t - o] : 0;
        __syncthreads();
        s[t] += v;
        __syncthreads();
    }
    float lut = rintf((float)s[t] * (255.0f / (float)AREA));
    lut = fminf(fmaxf(lut, 0.0f), 255.0f);
    g_lut[c][tile][t] = (unsigned char)lut;
}

// ------- passes 4/5: one row per block, row-fused pair-LUT, 1 LDS.64/pixel --
template <bool FINAL>
__global__ void k_apply(float* __restrict__ out) {
    int c = blockIdx.y, r = blockIdx.x, tid = threadIdx.x;
    __shared__ float2 lutP[9 * BINS];             // 18KB: (lut[x0], lut[x1]) per floor(fx) slot

    float fy  = ((float)r + 0.5f) * (1.0f / (float)THW) - 0.5f;
    float ffy = floorf(fy);
    int y0 = min(max((int)ffy, 0), TT - 1);
    int y1 = min(y0 + 1, TT - 1);
    float wy = fy - ffy, omy = 1.0f - wy;

    const unsigned char* L = &g_lut[c][0][0];
    for (int e = tid; e < 9 * BINS; e += 256) {
        int ix = e >> 8, f = e & 255;
        int xa = max(ix - 1, 0);
        int xb = min(xa + 1, TT - 1);
        float a = omy * (float)L[(y0 * TT + xa) * BINS + f] + wy * (float)L[(y1 * TT + xa) * BINS + f];
        float b = omy * (float)L[(y0 * TT + xb) * BINS + f] + wy * (float)L[(y1 * TT + xb) * BINS + f];
        lutP[e] = make_float2(a, b);
    }
    __syncthreads();

    bool cond2 = false; float vmin2 = 0.f, rng2 = 1.f;
    if (FINAL) {
        float vmax2 = __int_as_float(g_vmax2[c]);
        vmin2 = __int_as_float(g_vmin2[c]);
        cond2 = vmax2 > 0.0f;
        rng2  = fmaxf(vmax2 - vmin2, 1e-12f);
    }

    size_t rowbase = (size_t)c * NPIX + (size_t)r * WW;
    uint4 qw = ((const uint4*)(g_q + rowbase))[tid];            // 16 px per thread
    unsigned int mw = 0;
    if (FINAL) mw = ((const unsigned int*)(g_m + rowbase / 4))[tid];

    unsigned int wv[4] = {qw.x, qw.y, qw.z, qw.w};
    float lmin = F_INF, lmax = F_NINF;
    int colbase = tid * 16;

    #pragma unroll
    for (int w = 0; w < 4; w++) {
        float res[4];
        #pragma unroll
        for (int k = 0; k < 4; k++) {
            int col = colbase + w * 4 + k;
            unsigned int v = (wv[w] >> (8 * k)) & 255u;
            float fx  = ((float)col + 0.5f) * (1.0f / (float)THW) - 0.5f;
            float ffx = floorf(fx);
            float wx  = fx - ffx;
            int ix = (int)ffx + 1;                               // 0..8
            float y = 0.0f;
            if (v) {                                             // v==0 -> y=0, no lookup
                float2 pp = lutP[ix * BINS + (int)v];
                float eq = pp.x * (1.0f - wx) + pp.y * wx;
                y = eq * (1.0f / 255.0f);
            }
            if (FINAL) {
                unsigned int msk = (mw >> (8 * w + k)) & 1u;
                float scaled = (y - vmin2) / rng2 * 0.99607843137f + 0.0039215686f;
                res[k] = msk ? (cond2 ? scaled : 0.0039215686f) : y;
            } else {
                if (v) { lmin = fminf(lmin, y); lmax = fmaxf(lmax, y); }  // v>0 => masked
            }
        }
        if (FINAL) {
            float4 o4; o4.x = res[0]; o4.y = res[1]; o4.z = res[2]; o4.w = res[3];
            ((float4*)(out + rowbase))[tid * 4 + w] = o4;
        }
    }

    if (!FINAL) {
        __shared__ float smn[8], smx[8];
        #pragma unroll
        for (int o = 16; o; o >>= 1) {
            lmin = fminf(lmin, __shfl_down_sync(0xffffffffu, lmin, o));
            lmax = fmaxf(lmax, __shfl_down_sync(0xffffffffu, lmax, o));
        }
        if ((tid & 31) == 0) { smn[tid >> 5] = lmin; smx[tid >> 5] = lmax; }
        __syncthreads();
        if (tid == 0) {
            float a = F_INF, b = F_NINF;
            #pragma unroll
            for (int j = 0; j < 8; j++) { a = fminf(a, smn[j]); b = fmaxf(b, smx[j]); }
            atomicMin(&g_vmin2[c], __float_as_int(a));           // y >= 0 -> int order ok
            atomicMax(&g_vmax2[c], __float_as_int(b));
        }
    }
}

// ---------------------------------------------------------------------------
extern "C" void kernel_launch(void* const* d_in, const int* in_sizes, int n_in,
                              void* d_out, int out_size) {
    const float* X = (const float*)d_in[0];
    float* out = (float*)d_out;

    dim3 g1(MMB, CC);  k_minmax<<<g1, 256>>>(X);
    dim3 g2(512, CC);  k_quant <<<g2, 256>>>(X);
    dim3 g3(TT*TT, CC); k_lut  <<<g3, 256>>>();
    dim3 g4(HH, CC);
    k_apply<false><<<g4, 256>>>(out);
    k_apply<true> <<<g4, 256>>>(out);
}

// round 3
// speedup vs baseline: 1.4997x; 1.1611x over previous
#include <cuda_runtime.h>
#include <cstdint>

#define CC   4
#define HH   4096
#define WW   4096
#define NPIX (HH*WW)          // 16777216
#define TT   8
#define THW  512
#define BINS 256
#define AREA (THW*THW)        // 262144
#define CLV  40960            // int(40.0 * AREA / BINS)
#define MMB  1024             // minmax blocks per channel
#define SROWS 16              // rows per apply strip

// ---------------- scratch (static device globals; no allocation) ------------
__device__ unsigned char      g_q[(size_t)CC * NPIX];        // quantized value 0..255
__device__ unsigned char      g_m[(size_t)CC * NPIX / 4];    // mask nibble per float4 group
__device__ int                g_hist[CC][TT*TT][BINS];
__device__ unsigned char      g_lut[CC][TT*TT][BINS];
__device__ float2             g_part[CC * MMB];              // per-block (min,max) partials
__device__ int                g_vmin2[CC], g_vmax2[CC];      // float bits (y >= 0 -> int trick)
__device__ unsigned int       g_nz[CC], g_flag0[CC];
__device__ unsigned long long g_sum[CC];

#define F_INF  __int_as_float(0x7F800000)
#define F_NINF __int_as_float((int)0xFF800000)

// ---------------- pass 1: per-block masked min/max partials (+ init) --------
__global__ void k_minmax(const float* __restrict__ X) {
    int c = blockIdx.y, bx = blockIdx.x, tid = threadIdx.x;

    if (tid < 16) ((int*)g_hist)[(c * MMB + bx) * 16 + tid] = 0;
    if (c == 0 && bx == 0 && tid < CC) {
        g_vmin2[tid] = 0x7F800000;
        g_vmax2[tid] = (int)0xFF800000;
        g_nz[tid] = 0u; g_flag0[tid] = 0u; g_sum[tid] = 0ull;
    }

    const float4* p = (const float4*)(X + (size_t)c * NPIX);
    int base = bx * 4096;
    float vmin = F_INF, vmax = F_NINF;
    #pragma unroll 4
    for (int it = 0; it < 16; ++it) {
        float4 v = p[base + it * 256 + tid];
        if (v.x > 0.f) { vmin = fminf(vmin, v.x); vmax = fmaxf(vmax, v.x); }
        if (v.y > 0.f) { vmin = fminf(vmin, v.y); vmax = fmaxf(vmax, v.y); }
        if (v.z > 0.f) { vmin = fminf(vmin, v.z); vmax = fmaxf(vmax, v.z); }
        if (v.w > 0.f) { vmin = fminf(vmin, v.w); vmax = fmaxf(vmax, v.w); }
    }
    __shared__ float smn[8], smx[8];
    #pragma unroll
    for (int o = 16; o; o >>= 1) {
        vmin = fminf(vmin, __shfl_down_sync(0xffffffffu, vmin, o));
        vmax = fmaxf(vmax, __shfl_down_sync(0xffffffffu, vmax, o));
    }
    if ((tid & 31) == 0) { smn[tid >> 5] = vmin; smx[tid >> 5] = vmax; }
    __syncthreads();
    if (tid == 0) {
        float a = F_INF, b = F_NINF;
        #pragma unroll
        for (int j = 0; j < 8; j++) { a = fminf(a, smn[j]); b = fmaxf(b, smx[j]); }
        g_part[c * MMB + bx] = make_float2(a, b);
    }
}

// --------- pass 2: quantize + tile histograms + nz stats + zero-mask flag ---
__global__ void k_quant(const float* __restrict__ X) {
    int c = blockIdx.y, bx = blockIdx.x, tid = threadIdx.x;
    __shared__ int sh[TT * BINS];
    __shared__ float smn[8], smx[8], sfin[2];

    float vmin = F_INF, vmax = F_NINF;
    for (int j = tid; j < MMB; j += 256) {
        float2 pp = g_part[c * MMB + j];
        vmin = fminf(vmin, pp.x); vmax = fmaxf(vmax, pp.y);
    }
    #pragma unroll
    for (int o = 16; o; o >>= 1) {
        vmin = fminf(vmin, __shfl_down_sync(0xffffffffu, vmin, o));
        vmax = fmaxf(vmax, __shfl_down_sync(0xffffffffu, vmax, o));
    }
    if ((tid & 31) == 0) { smn[tid >> 5] = vmin; smx[tid >> 5] = vmax; }
    for (int j = tid; j < TT * BINS; j += 256) sh[j] = 0;
    __syncthreads();
    if (tid == 0) {
        float a = F_INF, b = F_NINF;
        #pragma unroll
        for (int j = 0; j < 8; j++) { a = fminf(a, smn[j]); b = fmaxf(b, smx[j]); }
        sfin[0] = a; sfin[1] = b;
    }
    __syncthreads();
    vmin = sfin[0]; vmax = sfin[1];
    bool  cond = vmax > 0.0f;
    float rng  = fmaxf(vmax - vmin, 1e-12f);
    float a255 = cond ? (255.0f / rng) : 0.0f;          // one div per thread, not per px
    float b255 = cond ? (-vmin * a255) : 0.0f;

    const float4* p  = (const float4*)(X + (size_t)c * NPIX);
    uchar4*       q8 = (uchar4*)(g_q + (size_t)c * NPIX);
    unsigned char* mp = g_m + (size_t)c * (NPIX / 4);

    int base = bx * 8192;
    int nzc = 0; unsigned int nzs = 0; bool az = false;

    #pragma unroll 4
    for (int it = 0; it < 32; ++it) {
        int i = base + it * 256 + tid;
        float4 v = p[i];
        int tx = (i & 1023) >> 7;
        float xs[4] = {v.x, v.y, v.z, v.w};
        unsigned char r[4]; unsigned int nib = 0;
        #pragma unroll
        for (int k = 0; k < 4; k++) {
            float x = xs[k];
            bool  m = x > 0.0f;
            float t = m ? fmaf(x, a255, b255) : 0.0f;
            float fb = fminf(fmaxf(floorf(t), 0.0f), 255.0f);
            int b = (int)fb;
            atomicAdd(&sh[tx * BINS + b], 1);
            nzc += (b != 0);
            nzs += (unsigned int)b;
            az  |= (m && b == 0);
            r[k] = (unsigned char)b;
            nib |= (m ? 1u : 0u) << k;
        }
        uchar4 o; o.x = r[0]; o.y = r[1]; o.z = r[2]; o.w = r[3];
        q8[i] = o;
        mp[i] = (unsigned char)nib;
    }
    __syncthreads();

    int ty = bx >> 6;
    for (int j = tid; j < TT * BINS; j += 256) {
        int v = sh[j];
        if (v) atomicAdd(&g_hist[c][ty * TT + (j >> 8)][j & 255], v);
    }
    unsigned int bal = __ballot_sync(0xffffffffu, az);
    #pragma unroll
    for (int o = 16; o; o >>= 1) {
        nzc += __shfl_down_sync(0xffffffffu, nzc, o);
        nzs += __shfl_down_sync(0xffffffffu, nzs, o);
    }
    if ((tid & 31) == 0) {
        atomicAdd(&g_nz[c], (unsigned int)nzc);
        atomicAdd(&g_sum[c], (unsigned long long)nzs);
        if (bal) atomicOr(&g_flag0[c], 1u);
    }
}

// ------------- pass 3: clip + redistribute + CDF -> u8 LUT (+ flag seed) ----
__global__ void k_lut() {
    int c = blockIdx.y, tile = blockIdx.x, t = threadIdx.x;
    __shared__ int s[BINS];

    if (tile == 0 && t == 0 && g_flag0[c]) {      // masked y==0 candidate exists
        g_vmin2[c] = 0;
        g_vmax2[c] = 0;
    }

    unsigned int nz = g_nz[c];
    int mean = 0;
    if (nz > 0) mean = (int)(g_sum[c] / (unsigned long long)nz);

    int h = g_hist[c][tile][t];
    if (nz > 0 && mean != 0) {
        int h0 = g_hist[c][tile][0];
        if (t == mean) h += h0;
        if (t == 0)    h  = 0;
    }

    int exc = max(h - CLV, 0);
    s[t] = exc; __syncthreads();
    #pragma unroll
    for (int o = 128; o; o >>= 1) { if (t < o) s[t] += s[t + o]; __syncthreads(); }
    int excess = s[0];
    __syncthreads();

    h = min(h, CLV);
    int batch = excess >> 8;
    int resid = excess & 255;
    int step  = 256 / max(resid, 1);
    h += batch + (((t % step) == 0 && (t / step) < resid) ? 1 : 0);

    s[t] = h; __syncthreads();
    #pragma unroll
    for (int o = 1; o < 256; o <<= 1) {
        int v = (t >= o) ? s[t - o] : 0;
        __syncthreads();
        s[t] += v;
        __syncthreads();
    }
    float lut = rintf((float)s[t] * (255.0f / (float)AREA));
    lut = fminf(fmaxf(lut, 0.0f), 255.0f);
    g_lut[c][tile][t] = (unsigned char)lut;
}

// -------- passes 4/5: 16-row strips, strip-resident float4 LUT,
// -------- 1 LDS.128 + 3 FMA per pixel --------------------------------------
template <bool FINAL>
__global__ void __launch_bounds__(256) k_apply(float* __restrict__ out) {
    int c = blockIdx.y, s = blockIdx.x, tid = threadIdx.x;
    int r0 = s * SROWS;
    __shared__ float4 lutP[9 * BINS];             // 36 KB: (a0, a1-a0, b0, b1-b0)

    // strip-constant y tile indices (floor(fy) boundaries are 16-row aligned)
    float fy0 = ((float)r0 + 0.5f) * (1.0f / (float)THW) - 0.5f;
    int y0 = min(max((int)floorf(fy0), 0), TT - 1);
    int y1 = min(y0 + 1, TT - 1);

    const unsigned char* L = &g_lut[c][0][0];
    #pragma unroll
    for (int e0 = 0; e0 < 9 * BINS; e0 += 256) {
        int e = e0 + tid;
        int ix = e >> 8, f = e & 255;
        int xa = max(ix - 1, 0);
        int xb = min(xa + 1, TT - 1);
        float a0 = (float)L[(y0 * TT + xa) * BINS + f];
        float a1 = (float)L[(y0 * TT + xb) * BINS + f];
        float b0 = (float)L[(y1 * TT + xa) * BINS + f];
        float b1 = (float)L[(y1 * TT + xb) * BINS + f];
        lutP[e] = make_float4(a0, a1 - a0, b0, b1 - b0);
    }
    __syncthreads();

    // uniform final-normalize constants (K1=0,K2=lo when cond2 false)
    float K1 = 0.0f, K2 = 0.0039215686f;
    if (FINAL) {
        float vmax2 = __int_as_float(g_vmax2[c]);
        float vmin2 = __int_as_float(g_vmin2[c]);
        if (vmax2 > 0.0f) {
            float rng2 = fmaxf(vmax2 - vmin2, 1e-12f);
            float k1 = 0.99607843137f / rng2;                 // (hi-lo)/rng
            K1 = k1 * (1.0f / 255.0f);                        // applied to eq directly
            K2 = 0.0039215686f - vmin2 * k1;
        }
    }

    // per-thread column constants: 16 contiguous columns share one ix slot
    float fx0 = ((float)(tid * 16) + 0.5f) * (1.0f / (float)THW) - 0.5f;
    float ffx = floorf(fx0);
    float wx0 = fx0 - ffx;                                    // exact (k/1024)
    const float4* rowL = lutP + ((int)ffx + 1) * BINS;

    int rowstride = WW / 16;                                  // uint4 (and uint) per row
    size_t base16 = ((size_t)c * NPIX + (size_t)r0 * WW) >> 4;
    const uint4* qp = ((const uint4*)g_q) + base16 + tid;
    const unsigned int* mp = ((const unsigned int*)g_m) + base16 + tid;
    float4* op = ((float4*)out) + (((size_t)c * NPIX + (size_t)r0 * WW) >> 2) + tid * 4;

    float lmin = F_INF, lmax = F_NINF;

    for (int rr = 0; rr < SROWS; ++rr) {
        float fyr = ((float)(r0 + rr) + 0.5f) * (1.0f / (float)THW) - 0.5f;
        float wy = fyr - floorf(fyr);

        uint4 qw = qp[rr * rowstride];
        unsigned int mw = 0;
        if (FINAL) mw = mp[rr * rowstride];
        unsigned int wv[4] = {qw.x, qw.y, qw.z, qw.w};

        #pragma unroll
        for (int w = 0; w < 4; w++) {
            float res[4];
            #pragma unroll
            for (int k = 0; k < 4; k++) {
                unsigned int v = (wv[w] >> (8 * k)) & 255u;
                float4 f = rowL[v];
                float wx = fmaf((float)(w * 4 + k), 1.0f / (float)THW, wx0);
                float px = fmaf(wx, f.y, f.x);
                float qx = fmaf(wx, f.w, f.z);
                float eq = fmaf(wy, qx - px, px);
                if (FINAL) {
                    eq = v ? eq : 0.0f;                       // y=0 for bin 0
                    float sc = fmaf(eq, K1, K2);
                    res[k] = ((mw >> (8 * w + k)) & 1u) ? sc : 0.0f;
                } else {
                    if (v) { lmin = fminf(lmin, eq); lmax = fmaxf(lmax, eq); }
                }
            }
            if (FINAL) {
                float4 o4; o4.x = res[0]; o4.y = res[1]; o4.z = res[2]; o4.w = res[3];
                op[(size_t)rr * (WW / 4) + w] = o4;
            }
        }
    }

    if (!FINAL) {
        __shared__ float smn[8], smx[8];
        #pragma unroll
        for (int o = 16; o; o >>= 1) {
            lmin = fminf(lmin, __shfl_down_sync(0xffffffffu, lmin, o));
            lmax = fmaxf(lmax, __shfl_down_sync(0xffffffffu, lmax, o));
        }
        if ((tid & 31) == 0) { smn[tid >> 5] = lmin; smx[tid >> 5] = lmax; }
        __syncthreads();
        if (tid == 0) {
            float a = F_INF, b = F_NINF;
            #pragma unroll
            for (int j = 0; j < 8; j++) { a = fminf(a, smn[j]); b = fmaxf(b, smx[j]); }
            // y = eq/255: division by positive constant is monotone -> commutes with min/max
            a = a * (1.0f / 255.0f);
            b = b * (1.0f / 255.0f);
            atomicMin(&g_vmin2[c], __float_as_int(a));
            atomicMax(&g_vmax2[c], __float_as_int(b));
        }
    }
}

// ---------------------------------------------------------------------------
extern "C" void kernel_launch(void* const* d_in, const int* in_sizes, int n_in,
                              void* d_out, int out_size) {
    const float* X = (const float*)d_in[0];
    float* out = (float*)d_out;

    dim3 g1(MMB, CC);        k_minmax<<<g1, 256>>>(X);
    dim3 g2(512, CC);        k_quant <<<g2, 256>>>(X);
    dim3 g3(TT*TT, CC);      k_lut   <<<g3, 256>>>();
    dim3 g4(HH/SROWS, CC);
    k_apply<false><<<g4, 256>>>(out);
    k_apply<true> <<<g4, 256>>>(out);
}

// round 4
// speedup vs baseline: 1.7359x; 1.1575x over previous
#include <cuda_runtime.h>
#include <cstdint>

#define CC   4
#define HH   4096
#define WW   4096
#define NPIX (HH*WW)          // 16777216
#define TT   8
#define THW  512
#define BINS 256
#define AREA (THW*THW)        // 262144
#define CLV  40960            // int(40.0 * AREA / BINS)
#define MMB  1024             // minmax blocks per channel
#define SROWS 16              // rows per apply strip

// ---------------- scratch (static device globals; no allocation) ------------
__device__ unsigned char      g_q[(size_t)CC * NPIX];        // quantized value 0..255
__device__ unsigned char      g_m[(size_t)CC * NPIX / 4];    // mask nibble per float4 group
__device__ int                g_hist[CC][TT*TT][BINS];
__device__ unsigned char      g_lut[CC][TT*TT][BINS];
__device__ float2             g_part[CC * MMB];              // per-block (min,max) partials
__device__ int                g_vmin2[CC], g_vmax2[CC];      // float bits (y >= 0 -> int trick)
__device__ unsigned int       g_nz[CC], g_flag0[CC];
__device__ unsigned long long g_sum[CC];

#define F_INF  __int_as_float(0x7F800000)
#define F_NINF __int_as_float((int)0xFF800000)

// pack two exactly-bf16-representable floats into one uint (lo, hi)
__device__ __forceinline__ unsigned int packbf(float lo, float hi) {
    return (__float_as_uint(lo) >> 16) | (__float_as_uint(hi) & 0xFFFF0000u);
}

// ---------------- pass 1: per-block masked min/max partials (+ init) --------
__global__ void k_minmax(const float* __restrict__ X) {
    int c = blockIdx.y, bx = blockIdx.x, tid = threadIdx.x;

    if (tid < 16) ((int*)g_hist)[(c * MMB + bx) * 16 + tid] = 0;
    if (c == 0 && bx == 0 && tid < CC) {
        g_vmin2[tid] = 0x7F800000;
        g_vmax2[tid] = (int)0xFF800000;
        g_nz[tid] = 0u; g_flag0[tid] = 0u; g_sum[tid] = 0ull;
    }

    const float4* p = (const float4*)(X + (size_t)c * NPIX);
    int base = bx * 4096;
    float vmin = F_INF, vmax = F_NINF;
    #pragma unroll 4
    for (int it = 0; it < 16; ++it) {
        float4 v = p[base + it * 256 + tid];
        if (v.x > 0.f) { vmin = fminf(vmin, v.x); vmax = fmaxf(vmax, v.x); }
        if (v.y > 0.f) { vmin = fminf(vmin, v.y); vmax = fmaxf(vmax, v.y); }
        if (v.z > 0.f) { vmin = fminf(vmin, v.z); vmax = fmaxf(vmax, v.z); }
        if (v.w > 0.f) { vmin = fminf(vmin, v.w); vmax = fmaxf(vmax, v.w); }
    }
    __shared__ float smn[8], smx[8];
    #pragma unroll
    for (int o = 16; o; o >>= 1) {
        vmin = fminf(vmin, __shfl_down_sync(0xffffffffu, vmin, o));
        vmax = fmaxf(vmax, __shfl_down_sync(0xffffffffu, vmax, o));
    }
    if ((tid & 31) == 0) { smn[tid >> 5] = vmin; smx[tid >> 5] = vmax; }
    __syncthreads();
    if (tid == 0) {
        float a = F_INF, b = F_NINF;
        #pragma unroll
        for (int j = 0; j < 8; j++) { a = fminf(a, smn[j]); b = fmaxf(b, smx[j]); }
        g_part[c * MMB + bx] = make_float2(a, b);
    }
}

// --------- pass 2: quantize + tile histograms + nz stats + zero-mask flag ---
__global__ void k_quant(const float* __restrict__ X) {
    int c = blockIdx.y, bx = blockIdx.x, tid = threadIdx.x;
    __shared__ int sh[TT * BINS];
    __shared__ float smn[8], smx[8], sfin[2];

    float vmin = F_INF, vmax = F_NINF;
    for (int j = tid; j < MMB; j += 256) {
        float2 pp = g_part[c * MMB + j];
        vmin = fminf(vmin, pp.x); vmax = fmaxf(vmax, pp.y);
    }
    #pragma unroll
    for (int o = 16; o; o >>= 1) {
        vmin = fminf(vmin, __shfl_down_sync(0xffffffffu, vmin, o));
        vmax = fmaxf(vmax, __shfl_down_sync(0xffffffffu, vmax, o));
    }
    if ((tid & 31) == 0) { smn[tid >> 5] = vmin; smx[tid >> 5] = vmax; }
    for (int j = tid; j < TT * BINS; j += 256) sh[j] = 0;
    __syncthreads();
    if (tid == 0) {
        float a = F_INF, b = F_NINF;
        #pragma unroll
        for (int j = 0; j < 8; j++) { a = fminf(a, smn[j]); b = fmaxf(b, smx[j]); }
        sfin[0] = a; sfin[1] = b;
    }
    __syncthreads();
    vmin = sfin[0]; vmax = sfin[1];
    bool  cond = vmax > 0.0f;
    float rng  = fmaxf(vmax - vmin, 1e-12f);
    float a255 = cond ? (255.0f / rng) : 0.0f;
    float b255 = cond ? (-vmin * a255) : 0.0f;

    const float4* p  = (const float4*)(X + (size_t)c * NPIX);
    uchar4*       q8 = (uchar4*)(g_q + (size_t)c * NPIX);
    unsigned char* mp = g_m + (size_t)c * (NPIX / 4);

    int base = bx * 8192;
    int nzc = 0; unsigned int nzs = 0; bool az = false;

    #pragma unroll 4
    for (int it = 0; it < 32; ++it) {
        int i = base + it * 256 + tid;
        float4 v = p[i];
        int tx = (i & 1023) >> 7;
        float xs[4] = {v.x, v.y, v.z, v.w};
        unsigned char r[4]; unsigned int nib = 0;
        #pragma unroll
        for (int k = 0; k < 4; k++) {
            float x = xs[k];
            bool  m = x > 0.0f;
            float t = m ? fmaf(x, a255, b255) : 0.0f;
            float fb = fminf(fmaxf(floorf(t), 0.0f), 255.0f);
            int b = (int)fb;
            atomicAdd(&sh[tx * BINS + b], 1);
            nzc += (b != 0);
            nzs += (unsigned int)b;
            az  |= (m && b == 0);
            r[k] = (unsigned char)b;
            nib |= (m ? 1u : 0u) << k;
        }
        uchar4 o; o.x = r[0]; o.y = r[1]; o.z = r[2]; o.w = r[3];
        q8[i] = o;
        mp[i] = (unsigned char)nib;
    }
    __syncthreads();

    int ty = bx >> 6;
    for (int j = tid; j < TT * BINS; j += 256) {
        int v = sh[j];
        if (v) atomicAdd(&g_hist[c][ty * TT + (j >> 8)][j & 255], v);
    }
    unsigned int bal = __ballot_sync(0xffffffffu, az);
    #pragma unroll
    for (int o = 16; o; o >>= 1) {
        nzc += __shfl_down_sync(0xffffffffu, nzc, o);
        nzs += __shfl_down_sync(0xffffffffu, nzs, o);
    }
    if ((tid & 31) == 0) {
        atomicAdd(&g_nz[c], (unsigned int)nzc);
        atomicAdd(&g_sum[c], (unsigned long long)nzs);
        if (bal) atomicOr(&g_flag0[c], 1u);
    }
}

// ------------- pass 3: clip + redistribute + CDF -> u8 LUT (+ flag seed) ----
__global__ void k_lut() {
    int c = blockIdx.y, tile = blockIdx.x, t = threadIdx.x;
    __shared__ int s[BINS];

    if (tile == 0 && t == 0 && g_flag0[c]) {      // masked y==0 candidate exists
        g_vmin2[c] = 0;
        g_vmax2[c] = 0;
    }

    unsigned int nz = g_nz[c];
    int mean = 0;
    if (nz > 0) mean = (int)(g_sum[c] / (unsigned long long)nz);

    int h = g_hist[c][tile][t];
    if (nz > 0 && mean != 0) {
        int h0 = g_hist[c][tile][0];
        if (t == mean) h += h0;
        if (t == 0)    h  = 0;
    }

    int exc = max(h - CLV, 0);
    s[t] = exc; __syncthreads();
    #pragma unroll
    for (int o = 128; o; o >>= 1) { if (t < o) s[t] += s[t + o]; __syncthreads(); }
    int excess = s[0];
    __syncthreads();

    h = min(h, CLV);
    int batch = excess >> 8;
    int resid = excess & 255;
    int step  = 256 / max(resid, 1);
    h += batch + (((t % step) == 0 && (t / step) < resid) ? 1 : 0);

    s[t] = h; __syncthreads();
    #pragma unroll
    for (int o = 1; o < 256; o <<= 1) {
        int v = (t >= o) ? s[t - o] : 0;
        __syncthreads();
        s[t] += v;
        __syncthreads();
    }
    float lut = rintf((float)s[t] * (255.0f / (float)AREA));
    lut = fminf(fmaxf(lut, 0.0f), 255.0f);
    g_lut[c][tile][t] = (unsigned char)lut;
}

// -------- passes 4/5: 16-row strips, bf16-packed strip LUT (uint2/entry),
// -------- 1 LDS.64 + 4 ALU + 3 FMA per pixel --------------------------------
template <bool FINAL>
__global__ void __launch_bounds__(256) k_apply(float* __restrict__ out) {
    int c = blockIdx.y, s = blockIdx.x, tid = threadIdx.x;
    int r0 = s * SROWS;
    __shared__ uint2 lutP[9 * BINS];              // 18 KB: bf16x2{a0,da}, bf16x2{b0,db}

    // strip-constant y tile indices (floor(fy) boundaries are 16-row aligned)
    float fy0 = ((float)r0 + 0.5f) * (1.0f / (float)THW) - 0.5f;
    int y0 = min(max((int)floorf(fy0), 0), TT - 1);
    int y1 = min(y0 + 1, TT - 1);

    const unsigned char* L = &g_lut[c][0][0];
    #pragma unroll
    for (int e0 = 0; e0 < 9 * BINS; e0 += 256) {
        int e = e0 + tid;
        int ix = e >> 8, f = e & 255;
        int xa = max(ix - 1, 0);
        int xb = min(xa + 1, TT - 1);
        if (f == 0) {                             // bin 0 never consulted -> force eq=0
            lutP[e] = make_uint2(0u, 0u);
        } else {
            float a0 = (float)L[(y0 * TT + xa) * BINS + f];
            float a1 = (float)L[(y0 * TT + xb) * BINS + f];
            float b0 = (float)L[(y1 * TT + xa) * BINS + f];
            float b1 = (float)L[(y1 * TT + xb) * BINS + f];
            lutP[e] = make_uint2(packbf(a0, a1 - a0), packbf(b0, b1 - b0));
        }
    }
    __syncthreads();

    // uniform final-normalize constants (K1=0,K2=lo when cond2 false)
    float K1 = 0.0f, K2 = 0.0039215686f;
    if (FINAL) {
        float vmax2 = __int_as_float(g_vmax2[c]);
        float vmin2 = __int_as_float(g_vmin2[c]);
        if (vmax2 > 0.0f) {
            float rng2 = fmaxf(vmax2 - vmin2, 1e-12f);
            float k1 = 0.99607843137f / rng2;
            K1 = k1 * (1.0f / 255.0f);            // applied to eq directly
            K2 = 0.0039215686f - vmin2 * k1;
        }
    }

    // per-thread column constants: 16 contiguous columns share one ix slot
    float fx0 = ((float)(tid * 16) + 0.5f) * (1.0f / (float)THW) - 0.5f;
    float ffx = floorf(fx0);
    float wx0 = fx0 - ffx;                        // exact (k/1024)
    const uint2* rowL = lutP + ((int)ffx + 1) * BINS;

    int rowstride = WW / 16;                      // uint4 (and uint) per row
    size_t base16 = ((size_t)c * NPIX + (size_t)r0 * WW) >> 4;
    const uint4* qp = ((const uint4*)g_q) + base16 + tid;
    const unsigned int* mp = ((const unsigned int*)g_m) + base16 + tid;
    float4* op = ((float4*)out) + (((size_t)c * NPIX + (size_t)r0 * WW) >> 2) + tid * 4;

    float lmin = F_INF, lmax = F_NINF;

    for (int rr = 0; rr < SROWS; ++rr) {
        float fyr = ((float)(r0 + rr) + 0.5f) * (1.0f / (float)THW) - 0.5f;
        float wy = fyr - floorf(fyr);

        uint4 qw = qp[rr * rowstride];
        unsigned int mw = 0;
        if (FINAL) mw = mp[rr * rowstride];
        unsigned int wv[4] = {qw.x, qw.y, qw.z, qw.w};

        #pragma unroll
        for (int w = 0; w < 4; w++) {
            float res[4];
            #pragma unroll
            for (int k = 0; k < 4; k++) {
                unsigned int v = (wv[w] >> (8 * k)) & 255u;
                uint2 e = rowL[v];
                float a0 = __int_as_float(e.x << 16);
                float da = __int_as_float(e.x & 0xFFFF0000u);
                float b0 = __int_as_float(e.y << 16);
                float db = __int_as_float(e.y & 0xFFFF0000u);
                float wx = fmaf((float)(w * 4 + k), 1.0f / (float)THW, wx0);
                float px = fmaf(wx, da, a0);
                float qx = fmaf(wx, db, b0);
                float eq = fmaf(wy, qx - px, px);  // == 0 automatically when v==0
                if (FINAL) {
                    float sc = fmaf(eq, K1, K2);
                    res[k] = ((mw >> (8 * w + k)) & 1u) ? sc : 0.0f;
                } else {
                    if (v) { lmin = fminf(lmin, eq); lmax = fmaxf(lmax, eq); }
                }
            }
            if (FINAL) {
                float4 o4; o4.x = res[0]; o4.y = res[1]; o4.z = res[2]; o4.w = res[3];
                op[(size_t)rr * (WW / 4) + w] = o4;
            }
        }
    }

    if (!FINAL) {
        __shared__ float smn[8], smx[8];
        #pragma unroll
        for (int o = 16; o; o >>= 1) {
            lmin = fminf(lmin, __shfl_down_sync(0xffffffffu, lmin, o));
            lmax = fmaxf(lmax, __shfl_down_sync(0xffffffffu, lmax, o));
        }
        if ((tid & 31) == 0) { smn[tid >> 5] = lmin; smx[tid >> 5] = lmax; }
        __syncthreads();
        if (tid == 0) {
            float a = F_INF, b = F_NINF;
            #pragma unroll
            for (int j = 0; j < 8; j++) { a = fminf(a, smn[j]); b = fmaxf(b, smx[j]); }
            // y = eq/255: division by positive constant is monotone
            a = a * (1.0f / 255.0f);
            b = b * (1.0f / 255.0f);
            atomicMin(&g_vmin2[c], __float_as_int(a));
            atomicMax(&g_vmax2[c], __float_as_int(b));
        }
    }
}

// ---------------------------------------------------------------------------
extern "C" void kernel_launch(void* const* d_in, const int* in_sizes, int n_in,
                              void* d_out, int out_size) {
    const float* X = (const float*)d_in[0];
    float* out = (float*)d_out;

    dim3 g1(MMB, CC);        k_minmax<<<g1, 256>>>(X);
    dim3 g2(512, CC);        k_quant <<<g2, 256>>>(X);
    dim3 g3(TT*TT, CC);      k_lut   <<<g3, 256>>>();
    dim3 g4(HH/SROWS, CC);
    k_apply<false><<<g4, 256>>>(out);
    k_apply<true> <<<g4, 256>>>(out);
}